// round 10
// baseline (speedup 1.0000x reference)
#include <cuda_runtime.h>
#include <math_constants.h>

// cummax along T for [B, T, H, C] = [16, 512, 64, 128] fp32.
//
// R9: software-pipelined (double-buffered) version of R7.
// Post-mortem chain:
//   - DRAM% tracks average outstanding load bytes/SM.
//   - R5/R7 plateau at ~75-77% because the load->maxchain->store batch
//     structure has ~50% duty cycle: zero loads outstanding during the
//     compute+store phase. UNROLL scales both phases -> invariant.
// Fix: prefetch batch i+1's 16 LDG.128 before processing/storing batch i.
// Loads stay outstanding continuously -> average in-flight ~doubles.
// Keeps: float4 (sustained-clock win), 1024 blocks @ 32 thr (6.92/SM wave
// balance), streaming ld/st, immediate offsets.

#define B_DIM 16
#define T_DIM 512
#define HC_DIM (64 * 128)            // 8192 floats per timestep
#define HC4 (HC_DIM / 4)             // 2048 float4 per timestep
#define UNROLL 16
#define NBATCH (T_DIM / UNROLL)      // 32 batches

__device__ __forceinline__ void load_batch(float4 (&v)[UNROLL], const float4* __restrict__ p) {
    #pragma unroll
    for (int i = 0; i < UNROLL; ++i)
        v[i] = __ldcs(p + (size_t)i * HC4);          // streaming LDG.128
}

__device__ __forceinline__ void scan_store_batch(float4 (&v)[UNROLL], float4* __restrict__ q,
                                                 float& mx, float& my, float& mz, float& mw) {
    #pragma unroll
    for (int i = 0; i < UNROLL; ++i) {
        mx = fmaxf(mx, v[i].x);  v[i].x = mx;
        my = fmaxf(my, v[i].y);  v[i].y = my;
        mz = fmaxf(mz, v[i].z);  v[i].z = mz;
        mw = fmaxf(mw, v[i].w);  v[i].w = mw;
    }
    #pragma unroll
    for (int i = 0; i < UNROLL; ++i)
        __stcs(q + (size_t)i * HC4, v[i]);           // streaming STG.128
}

__global__ __launch_bounds__(32)
void cummax_time_kernel_v4p(const float4* __restrict__ in, float4* __restrict__ out) {
    const unsigned col4 = blockIdx.x * blockDim.x + threadIdx.x;   // exact, no guard needed

    const unsigned b      = col4 / HC4;
    const unsigned inner4 = col4 % HC4;

    const size_t base = (size_t)b * T_DIM * HC4 + inner4;
    const float4* __restrict__ p = in + base;
    float4* __restrict__       q = out + base;

    const size_t S = (size_t)UNROLL * HC4;           // batch stride in float4

    float mx = -CUDART_INF_F, my = -CUDART_INF_F;
    float mz = -CUDART_INF_F, mw = -CUDART_INF_F;

    float4 va[UNROLL], vb[UNROLL];

    // Prologue: batch 0 in flight.
    load_batch(va, p);  p += S;

    // Steady state: 15 iterations x 2 batches. Each process/store phase runs
    // with the next batch's 16 LDG.128 already issued and outstanding.
    #pragma unroll 1
    for (int it = 0; it < (NBATCH - 2) / 2; ++it) {
        load_batch(vb, p);  p += S;                  // prefetch batch 2it+1
        scan_store_batch(va, q, mx, my, mz, mw);  q += S;   // retire batch 2it

        load_batch(va, p);  p += S;                  // prefetch batch 2it+2
        scan_store_batch(vb, q, mx, my, mz, mw);  q += S;   // retire batch 2it+1
    }

    // Epilogue: batches 30 and 31.
    load_batch(vb, p);
    scan_store_batch(va, q, mx, my, mz, mw);  q += S;
    scan_store_batch(vb, q, mx, my, mz, mw);
}

extern "C" void kernel_launch(void* const* d_in, const int* in_sizes, int n_in,
                              void* d_out, int out_size) {
    const float4* in = (const float4*)d_in[0];
    float4* out = (float4*)d_out;

    const int total_cols4 = B_DIM * HC4;              // 32768
    const int threads = 32;
    const int blocks = total_cols4 / threads;         // 1024 -> 6.92/SM

    cummax_time_kernel_v4p<<<blocks, threads>>>(in, out);
}